// round 4
// baseline (speedup 1.0000x reference)
#include <cuda_runtime.h>
#include <cuda_bf16.h>
#include <cstdint>
#include <cstddef>

#define B_ 4
#define T_ 2048
#define D_ 2048
#define H_ 16
#define M_ 8192              // B*T
#define NP 10368             // padded fused projection cols (81*128)
#define CQ 0
#define CK 2048
#define CV 4096
#define CA 6144
#define CG 8192
#define CB 10240

// ---------------- scratch (static device globals; no allocation) ----------------
__device__ __nv_bfloat16 g_xh[(size_t)M_ * D_];
__device__ __nv_bfloat16 g_xl[(size_t)M_ * D_];
__device__ __nv_bfloat16 g_Wh[(size_t)NP * D_];
__device__ __nv_bfloat16 g_Wl[(size_t)NP * D_];
__device__ float         g_P [(size_t)M_ * NP];
__device__ float         g_qkv[(size_t)M_ * 6144];
__device__ float         g_decay[(size_t)M_ * 2048];
__device__ float         g_beta[(size_t)M_ * H_];
__device__ float         g_oscan[(size_t)M_ * 2048];
__device__ __nv_bfloat16 g_yh[(size_t)M_ * 2048];
__device__ __nv_bfloat16 g_yl[(size_t)M_ * 2048];
__device__ __nv_bfloat16 g_W2h[(size_t)D_ * 2048];
__device__ __nv_bfloat16 g_W2l[(size_t)D_ * 2048];

// ---------------- small helpers ----------------
__device__ __forceinline__ float sigf(float z) { return 1.f / (1.f + __expf(-z)); }

__device__ __forceinline__ void ldm4(uint32_t* r, uint32_t addr) {
    asm volatile("ldmatrix.sync.aligned.m8n8.x4.shared.b16 {%0,%1,%2,%3}, [%4];"
                 : "=r"(r[0]), "=r"(r[1]), "=r"(r[2]), "=r"(r[3]) : "r"(addr));
}
__device__ __forceinline__ void mma16816(float* c, const uint32_t* a, const uint32_t* b) {
    asm volatile("mma.sync.aligned.m16n8k16.row.col.f32.bf16.bf16.f32 "
                 "{%0,%1,%2,%3},{%4,%5,%6,%7},{%8,%9},{%0,%1,%2,%3};"
                 : "+f"(c[0]), "+f"(c[1]), "+f"(c[2]), "+f"(c[3])
                 : "r"(a[0]), "r"(a[1]), "r"(a[2]), "r"(a[3]), "r"(b[0]), "r"(b[1]));
}
__device__ __forceinline__ void cpa16(uint32_t saddr, const void* gaddr) {
    asm volatile("cp.async.cg.shared.global [%0], [%1], 16;" :: "r"(saddr), "l"(gaddr));
}
__device__ __forceinline__ void cpcommit() { asm volatile("cp.async.commit_group;"); }
template <int N> __device__ __forceinline__ void cpwait() {
    asm volatile("cp.async.wait_group %0;" :: "n"(N));
}

// ---------------- split fp32 -> (hi, lo) bf16, float4-vectorized ----------------
__global__ void split_f32_v4(const float* __restrict__ src, __nv_bfloat16* __restrict__ hi,
                             __nv_bfloat16* __restrict__ lo, size_t n4) {
    size_t i = (size_t)blockIdx.x * blockDim.x + threadIdx.x;
    if (i >= n4) return;
    float4 v = ((const float4*)src)[i];
    __nv_bfloat16 hx = __float2bfloat16(v.x), hy = __float2bfloat16(v.y);
    __nv_bfloat16 hz = __float2bfloat16(v.z), hw = __float2bfloat16(v.w);
    __nv_bfloat162* hp = (__nv_bfloat162*)hi;
    __nv_bfloat162* lp = (__nv_bfloat162*)lo;
    hp[i * 2]     = __nv_bfloat162(hx, hy);
    hp[i * 2 + 1] = __nv_bfloat162(hz, hw);
    lp[i * 2]     = __nv_bfloat162(__float2bfloat16(v.x - __bfloat162float(hx)),
                                   __float2bfloat16(v.y - __bfloat162float(hy)));
    lp[i * 2 + 1] = __nv_bfloat162(__float2bfloat16(v.z - __bfloat162float(hz)),
                                   __float2bfloat16(v.w - __bfloat162float(hw)));
}

// ---------------- build fused+padded weight matrix, split, float4-vectorized ----------------
__global__ void build_wcat(const float* __restrict__ Wq, const float* __restrict__ Wk,
                           const float* __restrict__ Wv, const float* __restrict__ Wa,
                           const float* __restrict__ Wg, const float* __restrict__ Wb) {
    size_t i = (size_t)blockIdx.x * blockDim.x + threadIdx.x;   // over float4s
    if (i >= (size_t)NP * D_ / 4) return;
    int n = (int)(i / (D_ / 4));
    int d4 = (int)(i % (D_ / 4));
    float4 v = make_float4(0.f, 0.f, 0.f, 0.f);
    if      (n < 2048)  v = ((const float4*)Wq)[(size_t)n * (D_ / 4) + d4];
    else if (n < 4096)  v = ((const float4*)Wk)[(size_t)(n - 2048) * (D_ / 4) + d4];
    else if (n < 6144)  v = ((const float4*)Wv)[(size_t)(n - 4096) * (D_ / 4) + d4];
    else if (n < 8192)  v = ((const float4*)Wa)[(size_t)(n - 6144) * (D_ / 4) + d4];
    else if (n < 10240) v = ((const float4*)Wg)[(size_t)(n - 8192) * (D_ / 4) + d4];
    else if (n < 10256) v = ((const float4*)Wb)[(size_t)(n - 10240) * (D_ / 4) + d4];
    __nv_bfloat16 hx = __float2bfloat16(v.x), hy = __float2bfloat16(v.y);
    __nv_bfloat16 hz = __float2bfloat16(v.z), hw = __float2bfloat16(v.w);
    __nv_bfloat162* hp = (__nv_bfloat162*)g_Wh;
    __nv_bfloat162* lp = (__nv_bfloat162*)g_Wl;
    hp[i * 2]     = __nv_bfloat162(hx, hy);
    hp[i * 2 + 1] = __nv_bfloat162(hz, hw);
    lp[i * 2]     = __nv_bfloat162(__float2bfloat16(v.x - __bfloat162float(hx)),
                                   __float2bfloat16(v.y - __bfloat162float(hy)));
    lp[i * 2 + 1] = __nv_bfloat162(__float2bfloat16(v.z - __bfloat162float(hz)),
                                   __float2bfloat16(v.w - __bfloat162float(hw)));
}

// ---------------- split-bf16 GEMM: C[M,N] = A[M,K] * B[N,K]^T (fp32-class accuracy) ----------------
// BM=128, BN=128, BK=32, 256 threads (8 warps, 2x4), warp tile 64x32. 2 CTAs/SM.
__device__ __forceinline__ void gemm_issue_stage(
    uint32_t smem, int stage, int tid,
    const __nv_bfloat16* Ah, const __nv_bfloat16* Al,
    const __nv_bfloat16* Bh, const __nv_bfloat16* Bl,
    int m0, int n0, int k0, int Kd)
{
#pragma unroll
    for (int i = 0; i < 2; i++) {
        int idx = tid + i * 256;            // 0..511
        int row = idx >> 2, ch = idx & 3;   // 128 rows x 4 16B-chunks
        int pch = ch ^ ((row >> 1) & 3);    // XOR swizzle: conflict-free ldmatrix
        uint32_t so = smem + stage * 32768 + row * 64 + pch * 16;
        size_t ga = (size_t)(m0 + row) * Kd + k0 + ch * 8;
        size_t gb = (size_t)(n0 + row) * Kd + k0 + ch * 8;
        cpa16(so,         Ah + ga);
        cpa16(so + 8192,  Al + ga);
        cpa16(so + 16384, Bh + gb);
        cpa16(so + 24576, Bl + gb);
    }
}

__global__ void __launch_bounds__(256, 2) gemm_split(
    const __nv_bfloat16* __restrict__ Ah, const __nv_bfloat16* __restrict__ Al,
    const __nv_bfloat16* __restrict__ Bh, const __nv_bfloat16* __restrict__ Bl,
    float* __restrict__ C, int M, int N, int Kd)
{
    extern __shared__ char sm_[];
    uint32_t smem = (uint32_t)__cvta_generic_to_shared(sm_);
    int tid = threadIdx.x;
    int warp = tid >> 5, lane = tid & 31;
    int wm = warp >> 2, wn = warp & 3;
    int m0 = blockIdx.y * 128, n0 = blockIdx.x * 128;

    float acc[4][4][4];
#pragma unroll
    for (int a = 0; a < 4; a++)
#pragma unroll
        for (int b = 0; b < 4; b++)
#pragma unroll
            for (int c = 0; c < 4; c++) acc[a][b][c] = 0.f;

    int nkt = Kd >> 5;
    gemm_issue_stage(smem, 0, tid, Ah, Al, Bh, Bl, m0, n0, 0, Kd);
    cpcommit();

    for (int kt = 0; kt < nkt; kt++) {
        if (kt + 1 < nkt) {
            gemm_issue_stage(smem, (kt + 1) & 1, tid, Ah, Al, Bh, Bl, m0, n0, (kt + 1) * 32, Kd);
            cpcommit();
            cpwait<1>();
        } else {
            cpwait<0>();
        }
        __syncthreads();

        uint32_t base = smem + (kt & 1) * 32768;
#pragma unroll
        for (int k16 = 0; k16 < 2; k16++) {
            uint32_t a_h[4][4], a_l[4][4];
#pragma unroll
            for (int ms = 0; ms < 4; ms++) {
                int r = wm * 64 + ms * 16 + (lane & 15);
                int ch = k16 * 2 + (lane >> 4);
                int pch = ch ^ ((r >> 1) & 3);
                uint32_t ad = base + r * 64 + pch * 16;
                ldm4(a_h[ms], ad);
                ldm4(a_l[ms], ad + 8192);
            }
            uint32_t b_h[2][4], b_l[2][4];
#pragma unroll
            for (int ns = 0; ns < 2; ns++) {
                int r = wn * 32 + ns * 16 + (lane & 7) + ((lane >> 4) << 3);
                int ch = k16 * 2 + ((lane >> 3) & 1);
                int pch = ch ^ ((r >> 1) & 3);
                uint32_t ad = base + 16384 + r * 64 + pch * 16;
                ldm4(b_h[ns], ad);
                ldm4(b_l[ns], ad + 8192);
            }
#pragma unroll
            for (int ms = 0; ms < 4; ms++)
#pragma unroll
                for (int j = 0; j < 4; j++) {
                    const uint32_t* bhp = &b_h[j >> 1][(j & 1) * 2];
                    const uint32_t* blp = &b_l[j >> 1][(j & 1) * 2];
                    mma16816(acc[ms][j], a_h[ms], bhp);   // hi*hi
                    mma16816(acc[ms][j], a_h[ms], blp);   // hi*lo
                    mma16816(acc[ms][j], a_l[ms], bhp);   // lo*hi
                }
        }
        __syncthreads();
    }

#pragma unroll
    for (int ms = 0; ms < 4; ms++)
#pragma unroll
        for (int j = 0; j < 4; j++) {
            int row = m0 + wm * 64 + ms * 16 + (lane >> 2);
            int col = n0 + wn * 32 + j * 8 + (lane & 3) * 2;
            float2 v0; v0.x = acc[ms][j][0]; v0.y = acc[ms][j][1];
            float2 v1; v1.x = acc[ms][j][2]; v1.y = acc[ms][j][3];
            *(float2*)(C + (size_t)row * N + col)       = v0;
            *(float2*)(C + (size_t)(row + 8) * N + col) = v1;
        }
}

// ---------------- depthwise causal conv (K=4) + SiLU ----------------
__global__ void conv_silu(const float* __restrict__ cqw, const float* __restrict__ cqb,
                          const float* __restrict__ ckw, const float* __restrict__ ckb,
                          const float* __restrict__ cvw, const float* __restrict__ cvb) {
    size_t i = (size_t)blockIdx.x * blockDim.x + threadIdx.x;
    if (i >= (size_t)M_ * 6144) return;
    int c = (int)(i % 6144);
    size_t r = i / 6144;
    int t = (int)(r & (T_ - 1));
    const float* w;
    float bias;
    if (c < 2048)      { w = cqw + (size_t)c * 4;          bias = cqb[c]; }
    else if (c < 4096) { w = ckw + (size_t)(c - 2048) * 4; bias = ckb[c - 2048]; }
    else               { w = cvw + (size_t)(c - 4096) * 4; bias = cvb[c - 4096]; }
    const float* src = g_P + r * (size_t)NP + c;
    float acc = bias;
#pragma unroll
    for (int kk = 0; kk < 4; kk++) {
        int dt = kk - 3;
        if (t + dt >= 0) acc += w[kk] * src[(ptrdiff_t)dt * NP];
    }
    g_qkv[i] = acc * sigf(acc);
}

// ---------------- decay = max(sigmoid(a_pre+ba),1e-6) == exp(g); beta ----------------
__global__ void decay_kernel(const float* __restrict__ ba) {
    size_t i = (size_t)blockIdx.x * blockDim.x + threadIdx.x;
    if (i >= (size_t)M_ * 2048) return;
    int c = (int)(i % 2048);
    size_t r = i / 2048;
    float a = sigf(g_P[r * (size_t)NP + CA + c] + ba[c]);
    g_decay[i] = fmaxf(a, 1e-6f);
}
__global__ void beta_kernel(const float* __restrict__ bb) {
    size_t i = (size_t)blockIdx.x * blockDim.x + threadIdx.x;
    if (i >= (size_t)M_ * H_) return;
    int h = (int)(i % H_);
    size_t r = i / H_;
    g_beta[i] = sigf(g_P[r * (size_t)NP + CB + h] + bb[h]);
}

// ---------------- gated delta-rule scan ----------------
// block = (b,h, 64-col slice); 256 threads = 64 j x 4 k-slices; state in regs;
// k/q/d/v staged once per t into triple-buffered smem (broadcast reads).
struct __align__(16) SBuf {
    float k[128]; float d[128]; float q[128]; float v[64]; float beta; float pad[3];
};

__device__ __forceinline__ void scan_ld(SBuf* p, int t, int tid,
    const float* __restrict__ kb, const float* __restrict__ qb,
    const float* __restrict__ db, const float* __restrict__ vb,
    const float* __restrict__ bbp) {
    if (tid < 128) {
        p->k[tid] = kb[(size_t)t * 6144 + tid];
        p->d[tid] = db[(size_t)t * 2048 + tid];
    } else {
        int u = tid - 128;
        p->q[u] = qb[(size_t)t * 6144 + u];
        if (u < 64) p->v[u] = vb[(size_t)t * 6144 + u];
        if (u == 127) p->beta = bbp[(size_t)t * H_];
    }
}

__global__ void __launch_bounds__(256) kda_scan() {
    __shared__ SBuf sb[3];
    int tid = threadIdx.x;
    int bh = blockIdx.x;
    int b = bh >> 4, h = bh & 15;
    int jq = blockIdx.y;           // 0..1
    int jl = tid >> 2, ks = tid & 3;
    size_t rbase = (size_t)b * T_;

    const float* kb = g_qkv + rbase * 6144 + CK + h * 128;
    const float* qb = g_qkv + rbase * 6144 + CQ + h * 128;
    const float* db = g_decay + rbase * 2048 + h * 128;
    const float* vb = g_qkv + rbase * 6144 + CV + h * 128 + jq * 64;
    const float* bbp = g_beta + rbase * H_ + h;
    float* ob = g_oscan + rbase * 2048 + h * 128 + jq * 64 + jl;

    scan_ld(&sb[0], 0, tid, kb, qb, db, vb, bbp);
    scan_ld(&sb[1], 1, tid, kb, qb, db, vb, bbp);
    __syncthreads();

    float s[32];
#pragma unroll
    for (int i = 0; i < 32; i++) s[i] = 0.f;
    const float scale = 0.08838834764831845f;   // K^-0.5

    int cur = 0;
    for (int t = 0; t < T_; t++) {
        SBuf* cu = &sb[cur];
        int nxt2 = cur + 2; if (nxt2 >= 3) nxt2 -= 3;
        if (t + 2 < T_) scan_ld(&sb[nxt2], t + 2, tid, kb, qb, db, vb, bbp);

        const float4* k4 = (const float4*)(cu->k + (ks << 5));
        const float4* d4 = (const float4*)(cu->d + (ks << 5));
        const float4* q4 = (const float4*)(cu->q + (ks << 5));
        float vv = cu->v[jl];
        float bt = cu->beta;

        float4 kr[8];
#pragma unroll
        for (int i = 0; i < 8; i++) kr[i] = k4[i];

        float aa0 = 0.f, aa1 = 0.f, aa2 = 0.f, aa3 = 0.f;
#pragma unroll
        for (int i = 0; i < 8; i++) {
            float4 dd = d4[i];
            s[4*i]   *= dd.x;  s[4*i+1] *= dd.y;
            s[4*i+2] *= dd.z;  s[4*i+3] *= dd.w;
            aa0 = fmaf(kr[i].x, s[4*i],   aa0);
            aa1 = fmaf(kr[i].y, s[4*i+1], aa1);
            aa2 = fmaf(kr[i].z, s[4*i+2], aa2);
            aa3 = fmaf(kr[i].w, s[4*i+3], aa3);
        }
        float kdot = (aa0 + aa1) + (aa2 + aa3);
        kdot += __shfl_xor_sync(0xffffffffu, kdot, 1);
        kdot += __shfl_xor_sync(0xffffffffu, kdot, 2);

        float be = bt * (vv - kdot);

        float oo0 = 0.f, oo1 = 0.f, oo2 = 0.f, oo3 = 0.f;
#pragma unroll
        for (int i = 0; i < 8; i++) {
            float4 qq = q4[i];
            s[4*i]   = fmaf(be, kr[i].x, s[4*i]);
            s[4*i+1] = fmaf(be, kr[i].y, s[4*i+1]);
            s[4*i+2] = fmaf(be, kr[i].z, s[4*i+2]);
            s[4*i+3] = fmaf(be, kr[i].w, s[4*i+3]);
            oo0 = fmaf(qq.x, s[4*i],   oo0);
            oo1 = fmaf(qq.y, s[4*i+1], oo1);
            oo2 = fmaf(qq.z, s[4*i+2], oo2);
            oo3 = fmaf(qq.w, s[4*i+3], oo3);
        }
        float od = (oo0 + oo1) + (oo2 + oo3);
        od += __shfl_xor_sync(0xffffffffu, od, 1);
        od += __shfl_xor_sync(0xffffffffu, od, 2);
        if (ks == 0) ob[(size_t)t * 2048] = od * scale;

        cur++; if (cur >= 3) cur = 0;
        __syncthreads();
    }
}

// ---------------- per-head LayerNorm + sigmoid gate + split to bf16 hi/lo ----------------
__global__ void ln_gate(const float* __restrict__ ln_w, const float* __restrict__ ln_b) {
    int gwarp = (int)(((size_t)blockIdx.x * blockDim.x + threadIdx.x) >> 5);
    int lane = threadIdx.x & 31;
    if (gwarp >= M_ * H_) return;
    int h = gwarp & 15;
    size_t r = (size_t)(gwarp >> 4);

    const float* obp = g_oscan + r * 2048 + h * 128;
    float4 o4 = *(const float4*)(obp + lane * 4);
    float sum = o4.x + o4.y + o4.z + o4.w;
#pragma unroll
    for (int off = 16; off; off >>= 1) sum += __shfl_xor_sync(0xffffffffu, sum, off);
    float mu = sum * (1.f / 128.f);
    float dx = o4.x - mu, dy = o4.y - mu, dz = o4.z - mu, dw = o4.w - mu;
    float sq = dx * dx + dy * dy + dz * dz + dw * dw;
#pragma unroll
    for (int off = 16; off; off >>= 1) sq += __shfl_xor_sync(0xffffffffu, sq, off);
    float rs = rsqrtf(sq * (1.f / 128.f) + 1e-5f);

    float vals[4] = {dx, dy, dz, dw};
#pragma unroll
    for (int e = 0; e < 4; e++) {
        int jj = lane * 4 + e;
        float y = vals[e] * rs * ln_w[jj] + ln_b[jj];
        float gate = sigf(g_P[r * (size_t)NP + CG + h * 128 + jj]);
        y *= gate;
        size_t idx = r * 2048 + h * 128 + jj;
        __nv_bfloat16 hh = __float2bfloat16(y);
        g_yh[idx] = hh;
        g_yl[idx] = __float2bfloat16(y - __bfloat162float(hh));
    }
}

// ---------------- launch ----------------
extern "C" void kernel_launch(void* const* d_in, const int* in_sizes, int n_in,
                              void* d_out, int out_size) {
    const float* x    = (const float*)d_in[0];
    const float* Wq   = (const float*)d_in[1];
    const float* Wk   = (const float*)d_in[2];
    const float* Wv   = (const float*)d_in[3];
    const float* Wa   = (const float*)d_in[4];
    const float* ba   = (const float*)d_in[5];
    const float* Wb   = (const float*)d_in[6];
    const float* bb   = (const float*)d_in[7];
    const float* Wg   = (const float*)d_in[8];
    const float* Wo   = (const float*)d_in[9];
    const float* cqw  = (const float*)d_in[10];
    const float* cqb  = (const float*)d_in[11];
    const float* ckw  = (const float*)d_in[12];
    const float* ckb  = (const float*)d_in[13];
    const float* cvw  = (const float*)d_in[14];
    const float* cvb  = (const float*)d_in[15];
    const float* ln_w = (const float*)d_in[16];
    const float* ln_b = (const float*)d_in[17];
    float* out = (float*)d_out;

    static __nv_bfloat16 *pxh = nullptr, *pxl, *pWh, *pWl, *pyh, *pyl, *pW2h, *pW2l;
    static float *pP;
    if (!pxh) {
        cudaGetSymbolAddress((void**)&pxh, g_xh);
        cudaGetSymbolAddress((void**)&pxl, g_xl);
        cudaGetSymbolAddress((void**)&pWh, g_Wh);
        cudaGetSymbolAddress((void**)&pWl, g_Wl);
        cudaGetSymbolAddress((void**)&pP,  g_P);
        cudaGetSymbolAddress((void**)&pyh, g_yh);
        cudaGetSymbolAddress((void**)&pyl, g_yl);
        cudaGetSymbolAddress((void**)&pW2h, g_W2h);
        cudaGetSymbolAddress((void**)&pW2l, g_W2l);
        cudaFuncSetAttribute(gemm_split, cudaFuncAttributeMaxDynamicSharedMemorySize, 65536);
    }

    const int TPB = 256;

    // 1) split inputs to bf16 hi/lo (vectorized)
    split_f32_v4<<<(int)(((size_t)M_ * D_ / 4 + TPB - 1) / TPB), TPB>>>(x, pxh, pxl, (size_t)M_ * D_ / 4);
    build_wcat<<<(int)(((size_t)NP * D_ / 4 + TPB - 1) / TPB), TPB>>>(Wq, Wk, Wv, Wa, Wg, Wb);
    split_f32_v4<<<(int)(((size_t)D_ * 2048 / 4 + TPB - 1) / TPB), TPB>>>(Wo, pW2h, pW2l, (size_t)D_ * 2048 / 4);

    // 2) fused projection GEMM: P = x @ Wcat^T   (8192 x 10368 x 2048)
    gemm_split<<<dim3(NP / 128, M_ / 128), 256, 65536>>>(pxh, pxl, pWh, pWl, pP, M_, NP, D_);

    // 3) depthwise causal conv + SiLU on q,k,v
    conv_silu<<<(int)(((size_t)M_ * 6144 + TPB - 1) / TPB), TPB>>>(cqw, cqb, ckw, ckb, cvw, cvb);

    // 4) decay / beta
    decay_kernel<<<(int)(((size_t)M_ * 2048 + TPB - 1) / TPB), TPB>>>(ba);
    beta_kernel<<<(int)(((size_t)M_ * H_ + TPB - 1) / TPB), TPB>>>(bb);

    // 5) gated delta-rule scan (smem-staged, 128 blocks)
    kda_scan<<<dim3(B_ * H_, 2), 256>>>();

    // 6) LayerNorm + gate + bf16 split
    ln_gate<<<M_ * H_ / 8, 256>>>(ln_w, ln_b);

    // 7) output projection: out = y @ Wo^T   (8192 x 2048 x 2048)
    gemm_split<<<dim3(2048 / 128, M_ / 128), 256, 65536>>>(pyh, pyl, pW2h, pW2l, out, M_, 2048, D_);
}

// round 6
// speedup vs baseline: 1.0737x; 1.0737x over previous
#include <cuda_runtime.h>
#include <cuda_bf16.h>
#include <cstdint>
#include <cstddef>

#define B_ 4
#define T_ 2048
#define D_ 2048
#define H_ 16
#define M_ 8192              // B*T
#define NP 10368             // padded fused projection cols (81*128)
#define CQ 0
#define CK 2048
#define CV 4096
#define CA 6144
#define CG 8192
#define CB 10240

// ---------------- scratch (static device globals; no allocation) ----------------
__device__ __nv_bfloat16 g_xh[(size_t)M_ * D_];
__device__ __nv_bfloat16 g_xl[(size_t)M_ * D_];
__device__ __nv_bfloat16 g_Wh[(size_t)NP * D_];
__device__ __nv_bfloat16 g_Wl[(size_t)NP * D_];
__device__ float         g_P [(size_t)M_ * NP];
__device__ float         g_qkv[(size_t)M_ * 6144];
__device__ float         g_decay[(size_t)M_ * 2048];
__device__ float         g_beta[(size_t)M_ * H_];
__device__ float         g_oscan[(size_t)M_ * 2048];
__device__ __nv_bfloat16 g_yh[(size_t)M_ * 2048];
__device__ __nv_bfloat16 g_yl[(size_t)M_ * 2048];
__device__ __nv_bfloat16 g_W2h[(size_t)D_ * 2048];
__device__ __nv_bfloat16 g_W2l[(size_t)D_ * 2048];

// ---------------- small helpers ----------------
__device__ __forceinline__ float sigf(float z) { return 1.f / (1.f + __expf(-z)); }

__device__ __forceinline__ void ldm4(uint32_t* r, uint32_t addr) {
    asm volatile("ldmatrix.sync.aligned.m8n8.x4.shared.b16 {%0,%1,%2,%3}, [%4];"
                 : "=r"(r[0]), "=r"(r[1]), "=r"(r[2]), "=r"(r[3]) : "r"(addr));
}
__device__ __forceinline__ void mma16816(float* c, const uint32_t* a, const uint32_t* b) {
    asm volatile("mma.sync.aligned.m16n8k16.row.col.f32.bf16.bf16.f32 "
                 "{%0,%1,%2,%3},{%4,%5,%6,%7},{%8,%9},{%0,%1,%2,%3};"
                 : "+f"(c[0]), "+f"(c[1]), "+f"(c[2]), "+f"(c[3])
                 : "r"(a[0]), "r"(a[1]), "r"(a[2]), "r"(a[3]), "r"(b[0]), "r"(b[1]));
}
__device__ __forceinline__ void cpa16(uint32_t saddr, const void* gaddr) {
    asm volatile("cp.async.cg.shared.global [%0], [%1], 16;" :: "r"(saddr), "l"(gaddr));
}
__device__ __forceinline__ void cpcommit() { asm volatile("cp.async.commit_group;"); }
template <int N> __device__ __forceinline__ void cpwait() {
    asm volatile("cp.async.wait_group %0;" :: "n"(N));
}

// ---------------- split fp32 -> (hi, lo) bf16, float4-vectorized ----------------
__global__ void split_f32_v4(const float* __restrict__ src, __nv_bfloat16* __restrict__ hi,
                             __nv_bfloat16* __restrict__ lo, size_t n4) {
    size_t i = (size_t)blockIdx.x * blockDim.x + threadIdx.x;
    if (i >= n4) return;
    float4 v = ((const float4*)src)[i];
    __nv_bfloat16 hx = __float2bfloat16(v.x), hy = __float2bfloat16(v.y);
    __nv_bfloat16 hz = __float2bfloat16(v.z), hw = __float2bfloat16(v.w);
    __nv_bfloat162* hp = (__nv_bfloat162*)hi;
    __nv_bfloat162* lp = (__nv_bfloat162*)lo;
    hp[i * 2]     = __nv_bfloat162(hx, hy);
    hp[i * 2 + 1] = __nv_bfloat162(hz, hw);
    lp[i * 2]     = __nv_bfloat162(__float2bfloat16(v.x - __bfloat162float(hx)),
                                   __float2bfloat16(v.y - __bfloat162float(hy)));
    lp[i * 2 + 1] = __nv_bfloat162(__float2bfloat16(v.z - __bfloat162float(hz)),
                                   __float2bfloat16(v.w - __bfloat162float(hw)));
}

// ---------------- build fused+padded weight matrix, split, float4-vectorized ----------------
__global__ void build_wcat(const float* __restrict__ Wq, const float* __restrict__ Wk,
                           const float* __restrict__ Wv, const float* __restrict__ Wa,
                           const float* __restrict__ Wg, const float* __restrict__ Wb) {
    size_t i = (size_t)blockIdx.x * blockDim.x + threadIdx.x;   // over float4s
    if (i >= (size_t)NP * D_ / 4) return;
    int n = (int)(i / (D_ / 4));
    int d4 = (int)(i % (D_ / 4));
    float4 v = make_float4(0.f, 0.f, 0.f, 0.f);
    if      (n < 2048)  v = ((const float4*)Wq)[(size_t)n * (D_ / 4) + d4];
    else if (n < 4096)  v = ((const float4*)Wk)[(size_t)(n - 2048) * (D_ / 4) + d4];
    else if (n < 6144)  v = ((const float4*)Wv)[(size_t)(n - 4096) * (D_ / 4) + d4];
    else if (n < 8192)  v = ((const float4*)Wa)[(size_t)(n - 6144) * (D_ / 4) + d4];
    else if (n < 10240) v = ((const float4*)Wg)[(size_t)(n - 8192) * (D_ / 4) + d4];
    else if (n < 10256) v = ((const float4*)Wb)[(size_t)(n - 10240) * (D_ / 4) + d4];
    __nv_bfloat16 hx = __float2bfloat16(v.x), hy = __float2bfloat16(v.y);
    __nv_bfloat16 hz = __float2bfloat16(v.z), hw = __float2bfloat16(v.w);
    __nv_bfloat162* hp = (__nv_bfloat162*)g_Wh;
    __nv_bfloat162* lp = (__nv_bfloat162*)g_Wl;
    hp[i * 2]     = __nv_bfloat162(hx, hy);
    hp[i * 2 + 1] = __nv_bfloat162(hz, hw);
    lp[i * 2]     = __nv_bfloat162(__float2bfloat16(v.x - __bfloat162float(hx)),
                                   __float2bfloat16(v.y - __bfloat162float(hy)));
    lp[i * 2 + 1] = __nv_bfloat162(__float2bfloat16(v.z - __bfloat162float(hz)),
                                   __float2bfloat16(v.w - __bfloat162float(hw)));
}

// ---------------- split-bf16 GEMM: C[M,N] = A[M,K] * B[N,K]^T ----------------
// BM=128, BN=128, BK=32, 256 threads (8 warps, 2x4), warp tile 64x32.
// 3-stage cp.async pipeline (96KB smem), 2 CTAs/SM.
__device__ __forceinline__ void gemm_issue_stage(
    uint32_t smem, int stage, int tid,
    const __nv_bfloat16* Ah, const __nv_bfloat16* Al,
    const __nv_bfloat16* Bh, const __nv_bfloat16* Bl,
    int m0, int n0, int k0, int Kd)
{
#pragma unroll
    for (int i = 0; i < 2; i++) {
        int idx = tid + i * 256;            // 0..511
        int row = idx >> 2, ch = idx & 3;   // 128 rows x 4 16B-chunks
        int pch = ch ^ ((row >> 1) & 3);    // XOR swizzle: conflict-free ldmatrix
        uint32_t so = smem + stage * 32768 + row * 64 + pch * 16;
        size_t ga = (size_t)(m0 + row) * Kd + k0 + ch * 8;
        size_t gb = (size_t)(n0 + row) * Kd + k0 + ch * 8;
        cpa16(so,         Ah + ga);
        cpa16(so + 8192,  Al + ga);
        cpa16(so + 16384, Bh + gb);
        cpa16(so + 24576, Bl + gb);
    }
}

__global__ void __launch_bounds__(256, 2) gemm_split(
    const __nv_bfloat16* __restrict__ Ah, const __nv_bfloat16* __restrict__ Al,
    const __nv_bfloat16* __restrict__ Bh, const __nv_bfloat16* __restrict__ Bl,
    float* __restrict__ C, int M, int N, int Kd)
{
    extern __shared__ char sm_[];
    uint32_t smem = (uint32_t)__cvta_generic_to_shared(sm_);
    int tid = threadIdx.x;
    int warp = tid >> 5, lane = tid & 31;
    int wm = warp >> 2, wn = warp & 3;
    int m0 = blockIdx.y * 128, n0 = blockIdx.x * 128;

    float acc[4][4][4];
#pragma unroll
    for (int a = 0; a < 4; a++)
#pragma unroll
        for (int b = 0; b < 4; b++)
#pragma unroll
            for (int c = 0; c < 4; c++) acc[a][b][c] = 0.f;

    int nkt = Kd >> 5;
    gemm_issue_stage(smem, 0, tid, Ah, Al, Bh, Bl, m0, n0, 0, Kd);
    cpcommit();
    gemm_issue_stage(smem, 1, tid, Ah, Al, Bh, Bl, m0, n0, 32, Kd);
    cpcommit();

    int scur = 0, snext = 2;
    for (int kt = 0; kt < nkt; kt++) {
        if (kt == nkt - 1) { cpwait<0>(); } else { cpwait<1>(); }
        __syncthreads();
        if (kt + 2 < nkt) {
            gemm_issue_stage(smem, snext, tid, Ah, Al, Bh, Bl, m0, n0, (kt + 2) * 32, Kd);
            cpcommit();
        }

        uint32_t base = smem + scur * 32768;
#pragma unroll
        for (int k16 = 0; k16 < 2; k16++) {
            uint32_t a_h[4][4], a_l[4][4];
#pragma unroll
            for (int ms = 0; ms < 4; ms++) {
                int r = wm * 64 + ms * 16 + (lane & 15);
                int ch = k16 * 2 + (lane >> 4);
                int pch = ch ^ ((r >> 1) & 3);
                uint32_t ad = base + r * 64 + pch * 16;
                ldm4(a_h[ms], ad);
                ldm4(a_l[ms], ad + 8192);
            }
            uint32_t b_h[2][4], b_l[2][4];
#pragma unroll
            for (int ns = 0; ns < 2; ns++) {
                int r = wn * 32 + ns * 16 + (lane & 7) + ((lane >> 4) << 3);
                int ch = k16 * 2 + ((lane >> 3) & 1);
                int pch = ch ^ ((r >> 1) & 3);
                uint32_t ad = base + 16384 + r * 64 + pch * 16;
                ldm4(b_h[ns], ad);
                ldm4(b_l[ns], ad + 8192);
            }
#pragma unroll
            for (int ms = 0; ms < 4; ms++)
#pragma unroll
                for (int j = 0; j < 4; j++) {
                    const uint32_t* bhp = &b_h[j >> 1][(j & 1) * 2];
                    const uint32_t* blp = &b_l[j >> 1][(j & 1) * 2];
                    mma16816(acc[ms][j], a_h[ms], bhp);   // hi*hi
                    mma16816(acc[ms][j], a_h[ms], blp);   // hi*lo
                    mma16816(acc[ms][j], a_l[ms], bhp);   // lo*hi
                }
        }
        scur++; if (scur == 3) scur = 0;
        snext++; if (snext == 3) snext = 0;
    }

#pragma unroll
    for (int ms = 0; ms < 4; ms++)
#pragma unroll
        for (int j = 0; j < 4; j++) {
            int row = m0 + wm * 64 + ms * 16 + (lane >> 2);
            int col = n0 + wn * 32 + j * 8 + (lane & 3) * 2;
            float2 v0; v0.x = acc[ms][j][0]; v0.y = acc[ms][j][1];
            float2 v1; v1.x = acc[ms][j][2]; v1.y = acc[ms][j][3];
            *(float2*)(C + (size_t)row * N + col)       = v0;
            *(float2*)(C + (size_t)(row + 8) * N + col) = v1;
        }
}

// ---------------- depthwise causal conv (K=4) + SiLU ----------------
__global__ void conv_silu(const float* __restrict__ cqw, const float* __restrict__ cqb,
                          const float* __restrict__ ckw, const float* __restrict__ ckb,
                          const float* __restrict__ cvw, const float* __restrict__ cvb) {
    size_t i = (size_t)blockIdx.x * blockDim.x + threadIdx.x;
    if (i >= (size_t)M_ * 6144) return;
    int c = (int)(i % 6144);
    size_t r = i / 6144;
    int t = (int)(r & (T_ - 1));
    const float* w;
    float bias;
    if (c < 2048)      { w = cqw + (size_t)c * 4;          bias = cqb[c]; }
    else if (c < 4096) { w = ckw + (size_t)(c - 2048) * 4; bias = ckb[c - 2048]; }
    else               { w = cvw + (size_t)(c - 4096) * 4; bias = cvb[c - 4096]; }
    const float* src = g_P + r * (size_t)NP + c;
    float acc = bias;
#pragma unroll
    for (int kk = 0; kk < 4; kk++) {
        int dt = kk - 3;
        if (t + dt >= 0) acc += w[kk] * src[(ptrdiff_t)dt * NP];
    }
    g_qkv[i] = acc * sigf(acc);
}

// ---------------- decay = max(sigmoid(a_pre+ba),1e-6) == exp(g); beta ----------------
__global__ void decay_kernel(const float* __restrict__ ba) {
    size_t i = (size_t)blockIdx.x * blockDim.x + threadIdx.x;
    if (i >= (size_t)M_ * 2048) return;
    int c = (int)(i % 2048);
    size_t r = i / 2048;
    float a = sigf(g_P[r * (size_t)NP + CA + c] + ba[c]);
    g_decay[i] = fmaxf(a, 1e-6f);
}
__global__ void beta_kernel(const float* __restrict__ bb) {
    size_t i = (size_t)blockIdx.x * blockDim.x + threadIdx.x;
    if (i >= (size_t)M_ * H_) return;
    int h = (int)(i % H_);
    size_t r = i / H_;
    g_beta[i] = sigf(g_P[r * (size_t)NP + CB + h] + bb[h]);
}

// ---------------- gated delta-rule scan: warp-autonomous, no block syncs ----------------
// warp owns (b,h, 8 v-cols). lane = j(0..7)*4 + ks(0..3); each lane holds 32 state
// floats (k-slice ks). k/q/d loads are 4 distinct float4 streams broadcast to 8 lanes.
__global__ void __launch_bounds__(128) kda_scan() {
    int warp = threadIdx.x >> 5, lane = threadIdx.x & 31;
    int bh = blockIdx.x;                 // 0..63
    int b = bh >> 4, h = bh & 15;
    int wj = blockIdx.y * 4 + warp;      // 0..15 (16 warps per bh)
    int ks = lane & 3;                   // 32-wide k slice
    int j  = wj * 8 + (lane >> 2);       // v column 0..127
    size_t rbase = (size_t)b * T_;

    const float* kb  = g_qkv  + rbase * 6144 + CK + h * 128 + ks * 32;
    const float* qb  = g_qkv  + rbase * 6144 + CQ + h * 128 + ks * 32;
    const float* db  = g_decay + rbase * 2048 + h * 128 + ks * 32;
    const float* vb  = g_qkv  + rbase * 6144 + CV + h * 128 + j;
    const float* bbp = g_beta + rbase * H_ + h;
    float* ob = g_oscan + rbase * 2048 + h * 128 + j;

    float s[32];
#pragma unroll
    for (int i = 0; i < 32; i++) s[i] = 0.f;
    const float scale = 0.08838834764831845f;   // K^-0.5

    for (int t = 0; t < T_; t++) {
        const float4* k4 = (const float4*)(kb + (size_t)t * 6144);
        const float4* d4 = (const float4*)(db + (size_t)t * 2048);
        const float4* q4 = (const float4*)(qb + (size_t)t * 6144);
        float vv = vb[(size_t)t * 6144];
        float bt = bbp[(size_t)t * H_];

        float4 kr[8], dr[8];
#pragma unroll
        for (int i = 0; i < 8; i++) { kr[i] = k4[i]; dr[i] = d4[i]; }

        float a0 = 0.f, a1 = 0.f, a2 = 0.f, a3 = 0.f;
#pragma unroll
        for (int i = 0; i < 8; i++) {
            s[4*i]   *= dr[i].x;  s[4*i+1] *= dr[i].y;
            s[4*i+2] *= dr[i].z;  s[4*i+3] *= dr[i].w;
            a0 = fmaf(kr[i].x, s[4*i],   a0);
            a1 = fmaf(kr[i].y, s[4*i+1], a1);
            a2 = fmaf(kr[i].z, s[4*i+2], a2);
            a3 = fmaf(kr[i].w, s[4*i+3], a3);
        }
        float kdot = (a0 + a1) + (a2 + a3);
        kdot += __shfl_xor_sync(0xffffffffu, kdot, 1);
        kdot += __shfl_xor_sync(0xffffffffu, kdot, 2);

        float be = bt * (vv - kdot);

        float4 qr[8];
#pragma unroll
        for (int i = 0; i < 8; i++) qr[i] = q4[i];

        float o0 = 0.f, o1 = 0.f, o2 = 0.f, o3 = 0.f;
#pragma unroll
        for (int i = 0; i < 8; i++) {
            s[4*i]   = fmaf(be, kr[i].x, s[4*i]);
            s[4*i+1] = fmaf(be, kr[i].y, s[4*i+1]);
            s[4*i+2] = fmaf(be, kr[i].z, s[4*i+2]);
            s[4*i+3] = fmaf(be, kr[i].w, s[4*i+3]);
            o0 = fmaf(qr[i].x, s[4*i],   o0);
            o1 = fmaf(qr[i].y, s[4*i+1], o1);
            o2 = fmaf(qr[i].z, s[4*i+2], o2);
            o3 = fmaf(qr[i].w, s[4*i+3], o3);
        }
        float od = (o0 + o1) + (o2 + o3);
        od += __shfl_xor_sync(0xffffffffu, od, 1);
        od += __shfl_xor_sync(0xffffffffu, od, 2);
        if (ks == 0) ob[(size_t)t * 2048] = od * scale;
    }
}

// ---------------- per-head LayerNorm + sigmoid gate + split to bf16 hi/lo ----------------
__global__ void ln_gate(const float* __restrict__ ln_w, const float* __restrict__ ln_b) {
    int gwarp = (int)(((size_t)blockIdx.x * blockDim.x + threadIdx.x) >> 5);
    int lane = threadIdx.x & 31;
    if (gwarp >= M_ * H_) return;
    int h = gwarp & 15;
    size_t r = (size_t)(gwarp >> 4);

    const float* obp = g_oscan + r * 2048 + h * 128;
    float4 o4 = *(const float4*)(obp + lane * 4);
    float sum = o4.x + o4.y + o4.z + o4.w;
#pragma unroll
    for (int off = 16; off; off >>= 1) sum += __shfl_xor_sync(0xffffffffu, sum, off);
    float mu = sum * (1.f / 128.f);
    float dx = o4.x - mu, dy = o4.y - mu, dz = o4.z - mu, dw = o4.w - mu;
    float sq = dx * dx + dy * dy + dz * dz + dw * dw;
#pragma unroll
    for (int off = 16; off; off >>= 1) sq += __shfl_xor_sync(0xffffffffu, sq, off);
    float rs = rsqrtf(sq * (1.f / 128.f) + 1e-5f);

    float vals[4] = {dx, dy, dz, dw};
#pragma unroll
    for (int e = 0; e < 4; e++) {
        int jj = lane * 4 + e;
        float y = vals[e] * rs * ln_w[jj] + ln_b[jj];
        float gate = sigf(g_P[r * (size_t)NP + CG + h * 128 + jj]);
        y *= gate;
        size_t idx = r * 2048 + h * 128 + jj;
        __nv_bfloat16 hh = __float2bfloat16(y);
        g_yh[idx] = hh;
        g_yl[idx] = __float2bfloat16(y - __bfloat162float(hh));
    }
}

// ---------------- launch ----------------
extern "C" void kernel_launch(void* const* d_in, const int* in_sizes, int n_in,
                              void* d_out, int out_size) {
    const float* x    = (const float*)d_in[0];
    const float* Wq   = (const float*)d_in[1];
    const float* Wk   = (const float*)d_in[2];
    const float* Wv   = (const float*)d_in[3];
    const float* Wa   = (const float*)d_in[4];
    const float* ba   = (const float*)d_in[5];
    const float* Wb   = (const float*)d_in[6];
    const float* bb   = (const float*)d_in[7];
    const float* Wg   = (const float*)d_in[8];
    const float* Wo   = (const float*)d_in[9];
    const float* cqw  = (const float*)d_in[10];
    const float* cqb  = (const float*)d_in[11];
    const float* ckw  = (const float*)d_in[12];
    const float* ckb  = (const float*)d_in[13];
    const float* cvw  = (const float*)d_in[14];
    const float* cvb  = (const float*)d_in[15];
    const float* ln_w = (const float*)d_in[16];
    const float* ln_b = (const float*)d_in[17];
    float* out = (float*)d_out;

    static __nv_bfloat16 *pxh = nullptr, *pxl, *pWh, *pWl, *pyh, *pyl, *pW2h, *pW2l;
    static float *pP;
    if (!pxh) {
        cudaGetSymbolAddress((void**)&pxh, g_xh);
        cudaGetSymbolAddress((void**)&pxl, g_xl);
        cudaGetSymbolAddress((void**)&pWh, g_Wh);
        cudaGetSymbolAddress((void**)&pWl, g_Wl);
        cudaGetSymbolAddress((void**)&pP,  g_P);
        cudaGetSymbolAddress((void**)&pyh, g_yh);
        cudaGetSymbolAddress((void**)&pyl, g_yl);
        cudaGetSymbolAddress((void**)&pW2h, g_W2h);
        cudaGetSymbolAddress((void**)&pW2l, g_W2l);
        cudaFuncSetAttribute(gemm_split, cudaFuncAttributeMaxDynamicSharedMemorySize, 98304);
    }

    const int TPB = 256;

    // 1) split inputs to bf16 hi/lo (vectorized)
    split_f32_v4<<<(int)(((size_t)M_ * D_ / 4 + TPB - 1) / TPB), TPB>>>(x, pxh, pxl, (size_t)M_ * D_ / 4);
    build_wcat<<<(int)(((size_t)NP * D_ / 4 + TPB - 1) / TPB), TPB>>>(Wq, Wk, Wv, Wa, Wg, Wb);
    split_f32_v4<<<(int)(((size_t)D_ * 2048 / 4 + TPB - 1) / TPB), TPB>>>(Wo, pW2h, pW2l, (size_t)D_ * 2048 / 4);

    // 2) fused projection GEMM: P = x @ Wcat^T   (8192 x 10368 x 2048)
    gemm_split<<<dim3(NP / 128, M_ / 128), 256, 98304>>>(pxh, pxl, pWh, pWl, pP, M_, NP, D_);

    // 3) depthwise causal conv + SiLU on q,k,v
    conv_silu<<<(int)(((size_t)M_ * 6144 + TPB - 1) / TPB), TPB>>>(cqw, cqb, ckw, ckb, cvw, cvb);

    // 4) decay / beta
    decay_kernel<<<(int)(((size_t)M_ * 2048 + TPB - 1) / TPB), TPB>>>(ba);
    beta_kernel<<<(int)(((size_t)M_ * H_ + TPB - 1) / TPB), TPB>>>(bb);

    // 5) gated delta-rule scan (warp-autonomous, 256 blocks x 4 warps)
    kda_scan<<<dim3(B_ * H_, 4), 128>>>();

    // 6) LayerNorm + gate + bf16 split
    ln_gate<<<M_ * H_ / 8, 256>>>(ln_w, ln_b);

    // 7) output projection: out = y @ Wo^T   (8192 x 2048 x 2048)
    gemm_split<<<dim3(2048 / 128, M_ / 128), 256, 98304>>>(pyh, pyl, pW2h, pW2l, out, M_, 2048, D_);
}

// round 7
// speedup vs baseline: 1.4088x; 1.3121x over previous
#include <cuda_runtime.h>
#include <cuda_bf16.h>
#include <cstdint>
#include <cstddef>

#define B_ 4
#define T_ 2048
#define D_ 2048
#define H_ 16
#define M_ 8192              // B*T
#define NP 10368             // padded fused projection cols (81*128)
#define CQ 0
#define CK 2048
#define CV 4096
#define CA 6144
#define CG 8192
#define CB 10240

// ---------------- scratch (static device globals; no allocation) ----------------
__device__ __nv_bfloat16 g_xh[(size_t)M_ * D_];
__device__ __nv_bfloat16 g_xl[(size_t)M_ * D_];
__device__ __nv_bfloat16 g_Wh[(size_t)NP * D_];
__device__ __nv_bfloat16 g_Wl[(size_t)NP * D_];
__device__ float         g_P [(size_t)M_ * NP];
__device__ float         g_qkv[(size_t)M_ * 6144];
__device__ float         g_decay[(size_t)M_ * 2048];
__device__ float         g_beta[(size_t)M_ * H_];
__device__ float         g_oscan[(size_t)M_ * 2048];
__device__ __nv_bfloat16 g_yh[(size_t)M_ * 2048];
__device__ __nv_bfloat16 g_yl[(size_t)M_ * 2048];
__device__ __nv_bfloat16 g_W2h[(size_t)D_ * 2048];
__device__ __nv_bfloat16 g_W2l[(size_t)D_ * 2048];

// ---------------- small helpers ----------------
__device__ __forceinline__ float sigf(float z) { return 1.f / (1.f + __expf(-z)); }

__device__ __forceinline__ void ldm4(uint32_t* r, uint32_t addr) {
    asm volatile("ldmatrix.sync.aligned.m8n8.x4.shared.b16 {%0,%1,%2,%3}, [%4];"
                 : "=r"(r[0]), "=r"(r[1]), "=r"(r[2]), "=r"(r[3]) : "r"(addr));
}
__device__ __forceinline__ void mma16816(float* c, const uint32_t* a, const uint32_t* b) {
    asm volatile("mma.sync.aligned.m16n8k16.row.col.f32.bf16.bf16.f32 "
                 "{%0,%1,%2,%3},{%4,%5,%6,%7},{%8,%9},{%0,%1,%2,%3};"
                 : "+f"(c[0]), "+f"(c[1]), "+f"(c[2]), "+f"(c[3])
                 : "r"(a[0]), "r"(a[1]), "r"(a[2]), "r"(a[3]), "r"(b[0]), "r"(b[1]));
}
__device__ __forceinline__ void cpa16(uint32_t saddr, const void* gaddr) {
    asm volatile("cp.async.cg.shared.global [%0], [%1], 16;" :: "r"(saddr), "l"(gaddr));
}
__device__ __forceinline__ void cpcommit() { asm volatile("cp.async.commit_group;"); }
template <int N> __device__ __forceinline__ void cpwait() {
    asm volatile("cp.async.wait_group %0;" :: "n"(N));
}

// ---------------- split fp32 -> (hi, lo) bf16, float4-vectorized ----------------
__global__ void split_f32_v4(const float* __restrict__ src, __nv_bfloat16* __restrict__ hi,
                             __nv_bfloat16* __restrict__ lo, size_t n4) {
    size_t i = (size_t)blockIdx.x * blockDim.x + threadIdx.x;
    if (i >= n4) return;
    float4 v = ((const float4*)src)[i];
    __nv_bfloat16 hx = __float2bfloat16(v.x), hy = __float2bfloat16(v.y);
    __nv_bfloat16 hz = __float2bfloat16(v.z), hw = __float2bfloat16(v.w);
    __nv_bfloat162* hp = (__nv_bfloat162*)hi;
    __nv_bfloat162* lp = (__nv_bfloat162*)lo;
    hp[i * 2]     = __nv_bfloat162(hx, hy);
    hp[i * 2 + 1] = __nv_bfloat162(hz, hw);
    lp[i * 2]     = __nv_bfloat162(__float2bfloat16(v.x - __bfloat162float(hx)),
                                   __float2bfloat16(v.y - __bfloat162float(hy)));
    lp[i * 2 + 1] = __nv_bfloat162(__float2bfloat16(v.z - __bfloat162float(hz)),
                                   __float2bfloat16(v.w - __bfloat162float(hw)));
}

// ---------------- build fused+padded weight matrix, split, float4-vectorized ----------------
__global__ void build_wcat(const float* __restrict__ Wq, const float* __restrict__ Wk,
                           const float* __restrict__ Wv, const float* __restrict__ Wa,
                           const float* __restrict__ Wg, const float* __restrict__ Wb) {
    size_t i = (size_t)blockIdx.x * blockDim.x + threadIdx.x;   // over float4s
    if (i >= (size_t)NP * D_ / 4) return;
    int n = (int)(i / (D_ / 4));
    int d4 = (int)(i % (D_ / 4));
    float4 v = make_float4(0.f, 0.f, 0.f, 0.f);
    if      (n < 2048)  v = ((const float4*)Wq)[(size_t)n * (D_ / 4) + d4];
    else if (n < 4096)  v = ((const float4*)Wk)[(size_t)(n - 2048) * (D_ / 4) + d4];
    else if (n < 6144)  v = ((const float4*)Wv)[(size_t)(n - 4096) * (D_ / 4) + d4];
    else if (n < 8192)  v = ((const float4*)Wa)[(size_t)(n - 6144) * (D_ / 4) + d4];
    else if (n < 10240) v = ((const float4*)Wg)[(size_t)(n - 8192) * (D_ / 4) + d4];
    else if (n < 10256) v = ((const float4*)Wb)[(size_t)(n - 10240) * (D_ / 4) + d4];
    __nv_bfloat16 hx = __float2bfloat16(v.x), hy = __float2bfloat16(v.y);
    __nv_bfloat16 hz = __float2bfloat16(v.z), hw = __float2bfloat16(v.w);
    __nv_bfloat162* hp = (__nv_bfloat162*)g_Wh;
    __nv_bfloat162* lp = (__nv_bfloat162*)g_Wl;
    hp[i * 2]     = __nv_bfloat162(hx, hy);
    hp[i * 2 + 1] = __nv_bfloat162(hz, hw);
    lp[i * 2]     = __nv_bfloat162(__float2bfloat16(v.x - __bfloat162float(hx)),
                                   __float2bfloat16(v.y - __bfloat162float(hy)));
    lp[i * 2 + 1] = __nv_bfloat162(__float2bfloat16(v.z - __bfloat162float(hz)),
                                   __float2bfloat16(v.w - __bfloat162float(hw)));
}

// ---------------- split-bf16 GEMM: C[M,N] = A[M,K] * B[N,K]^T (fp32-class accuracy) ----------------
// BM=128, BN=128, BK=32, 256 threads (8 warps, 2x4), warp tile 64x32.
// 2-stage cp.async pipeline, 2 CTAs/SM (measured best: 2.25ms on 8192x10368x2048).
__device__ __forceinline__ void gemm_issue_stage(
    uint32_t smem, int stage, int tid,
    const __nv_bfloat16* Ah, const __nv_bfloat16* Al,
    const __nv_bfloat16* Bh, const __nv_bfloat16* Bl,
    int m0, int n0, int k0, int Kd)
{
#pragma unroll
    for (int i = 0; i < 2; i++) {
        int idx = tid + i * 256;            // 0..511
        int row = idx >> 2, ch = idx & 3;   // 128 rows x 4 16B-chunks
        int pch = ch ^ ((row >> 1) & 3);    // XOR swizzle: conflict-free ldmatrix
        uint32_t so = smem + stage * 32768 + row * 64 + pch * 16;
        size_t ga = (size_t)(m0 + row) * Kd + k0 + ch * 8;
        size_t gb = (size_t)(n0 + row) * Kd + k0 + ch * 8;
        cpa16(so,         Ah + ga);
        cpa16(so + 8192,  Al + ga);
        cpa16(so + 16384, Bh + gb);
        cpa16(so + 24576, Bl + gb);
    }
}

__global__ void __launch_bounds__(256, 2) gemm_split(
    const __nv_bfloat16* __restrict__ Ah, const __nv_bfloat16* __restrict__ Al,
    const __nv_bfloat16* __restrict__ Bh, const __nv_bfloat16* __restrict__ Bl,
    float* __restrict__ C, int M, int N, int Kd)
{
    extern __shared__ char sm_[];
    uint32_t smem = (uint32_t)__cvta_generic_to_shared(sm_);
    int tid = threadIdx.x;
    int warp = tid >> 5, lane = tid & 31;
    int wm = warp >> 2, wn = warp & 3;
    int m0 = blockIdx.y * 128, n0 = blockIdx.x * 128;

    float acc[4][4][4];
#pragma unroll
    for (int a = 0; a < 4; a++)
#pragma unroll
        for (int b = 0; b < 4; b++)
#pragma unroll
            for (int c = 0; c < 4; c++) acc[a][b][c] = 0.f;

    int nkt = Kd >> 5;
    gemm_issue_stage(smem, 0, tid, Ah, Al, Bh, Bl, m0, n0, 0, Kd);
    cpcommit();

    for (int kt = 0; kt < nkt; kt++) {
        if (kt + 1 < nkt) {
            gemm_issue_stage(smem, (kt + 1) & 1, tid, Ah, Al, Bh, Bl, m0, n0, (kt + 1) * 32, Kd);
            cpcommit();
            cpwait<1>();
        } else {
            cpwait<0>();
        }
        __syncthreads();

        uint32_t base = smem + (kt & 1) * 32768;
#pragma unroll
        for (int k16 = 0; k16 < 2; k16++) {
            uint32_t a_h[4][4], a_l[4][4];
#pragma unroll
            for (int ms = 0; ms < 4; ms++) {
                int r = wm * 64 + ms * 16 + (lane & 15);
                int ch = k16 * 2 + (lane >> 4);
                int pch = ch ^ ((r >> 1) & 3);
                uint32_t ad = base + r * 64 + pch * 16;
                ldm4(a_h[ms], ad);
                ldm4(a_l[ms], ad + 8192);
            }
            uint32_t b_h[2][4], b_l[2][4];
#pragma unroll
            for (int ns = 0; ns < 2; ns++) {
                int r = wn * 32 + ns * 16 + (lane & 7) + ((lane >> 4) << 3);
                int ch = k16 * 2 + ((lane >> 3) & 1);
                int pch = ch ^ ((r >> 1) & 3);
                uint32_t ad = base + 16384 + r * 64 + pch * 16;
                ldm4(b_h[ns], ad);
                ldm4(b_l[ns], ad + 8192);
            }
#pragma unroll
            for (int ms = 0; ms < 4; ms++)
#pragma unroll
                for (int j = 0; j < 4; j++) {
                    const uint32_t* bhp = &b_h[j >> 1][(j & 1) * 2];
                    const uint32_t* blp = &b_l[j >> 1][(j & 1) * 2];
                    mma16816(acc[ms][j], a_h[ms], bhp);   // hi*hi
                    mma16816(acc[ms][j], a_h[ms], blp);   // hi*lo
                    mma16816(acc[ms][j], a_l[ms], bhp);   // lo*hi
                }
        }
        __syncthreads();
    }

#pragma unroll
    for (int ms = 0; ms < 4; ms++)
#pragma unroll
        for (int j = 0; j < 4; j++) {
            int row = m0 + wm * 64 + ms * 16 + (lane >> 2);
            int col = n0 + wn * 32 + j * 8 + (lane & 3) * 2;
            float2 v0; v0.x = acc[ms][j][0]; v0.y = acc[ms][j][1];
            float2 v1; v1.x = acc[ms][j][2]; v1.y = acc[ms][j][3];
            *(float2*)(C + (size_t)row * N + col)       = v0;
            *(float2*)(C + (size_t)(row + 8) * N + col) = v1;
        }
}

// ---------------- depthwise causal conv (K=4) + SiLU ----------------
__global__ void conv_silu(const float* __restrict__ cqw, const float* __restrict__ cqb,
                          const float* __restrict__ ckw, const float* __restrict__ ckb,
                          const float* __restrict__ cvw, const float* __restrict__ cvb) {
    size_t i = (size_t)blockIdx.x * blockDim.x + threadIdx.x;
    if (i >= (size_t)M_ * 6144) return;
    int c = (int)(i % 6144);
    size_t r = i / 6144;
    int t = (int)(r & (T_ - 1));
    const float* w;
    float bias;
    if (c < 2048)      { w = cqw + (size_t)c * 4;          bias = cqb[c]; }
    else if (c < 4096) { w = ckw + (size_t)(c - 2048) * 4; bias = ckb[c - 2048]; }
    else               { w = cvw + (size_t)(c - 4096) * 4; bias = cvb[c - 4096]; }
    const float* src = g_P + r * (size_t)NP + c;
    float acc = bias;
#pragma unroll
    for (int kk = 0; kk < 4; kk++) {
        int dt = kk - 3;
        if (t + dt >= 0) acc += w[kk] * src[(ptrdiff_t)dt * NP];
    }
    g_qkv[i] = acc * sigf(acc);
}

// ---------------- decay = max(sigmoid(a_pre+ba),1e-6) == exp(g); beta ----------------
__global__ void decay_kernel(const float* __restrict__ ba) {
    size_t i = (size_t)blockIdx.x * blockDim.x + threadIdx.x;
    if (i >= (size_t)M_ * 2048) return;
    int c = (int)(i % 2048);
    size_t r = i / 2048;
    float a = sigf(g_P[r * (size_t)NP + CA + c] + ba[c]);
    g_decay[i] = fmaxf(a, 1e-6f);
}
__global__ void beta_kernel(const float* __restrict__ bb) {
    size_t i = (size_t)blockIdx.x * blockDim.x + threadIdx.x;
    if (i >= (size_t)M_ * H_) return;
    int h = (int)(i % H_);
    size_t r = i / H_;
    g_beta[i] = sigf(g_P[r * (size_t)NP + CB + h] + bb[h]);
}

// ---------------- gated delta-rule scan: 4096 warps, 16-lane k-slices ----------------
// warp owns (b,h, 2 v-cols). lane = jh(0..1)*16 + ks(0..15); each lane holds 8 state
// floats (8 k-channels). k/q/d loads: halves of the warp load identical addresses
// (HW broadcast); reductions are 4-shfl butterflies within 16-lane groups.
__global__ void __launch_bounds__(128) kda_scan() {
    int warp = threadIdx.x >> 5, lane = threadIdx.x & 31;
    int bh = blockIdx.x;                 // 0..63
    int b = bh >> 4, h = bh & 15;
    int wj = blockIdx.y * 4 + warp;      // 0..63 (64 warps per bh)
    int ks = lane & 15;                  // 8-channel k slice
    int j  = wj * 2 + (lane >> 4);       // v column 0..127
    size_t rbase = (size_t)b * T_;

    const float* kb  = g_qkv   + rbase * 6144 + CK + h * 128 + ks * 8;
    const float* qb  = g_qkv   + rbase * 6144 + CQ + h * 128 + ks * 8;
    const float* db  = g_decay + rbase * 2048 + h * 128 + ks * 8;
    const float* vb  = g_qkv   + rbase * 6144 + CV + h * 128 + j;
    const float* bbp = g_beta  + rbase * H_ + h;
    float* ob = g_oscan + rbase * 2048 + h * 128 + j;

    float s[8];
#pragma unroll
    for (int i = 0; i < 8; i++) s[i] = 0.f;
    const float scale = 0.08838834764831845f;   // K^-0.5

    for (int t = 0; t < T_; t++) {
        const float4* k4 = (const float4*)(kb + (size_t)t * 6144);
        const float4* d4 = (const float4*)(db + (size_t)t * 2048);
        const float4* q4 = (const float4*)(qb + (size_t)t * 6144);
        float vv = vb[(size_t)t * 6144];
        float bt = bbp[(size_t)t * H_];

        float4 kr0 = k4[0], kr1 = k4[1];
        float4 dd0 = d4[0], dd1 = d4[1];
        float4 qq0 = q4[0], qq1 = q4[1];

        s[0] *= dd0.x; s[1] *= dd0.y; s[2] *= dd0.z; s[3] *= dd0.w;
        s[4] *= dd1.x; s[5] *= dd1.y; s[6] *= dd1.z; s[7] *= dd1.w;

        float a0 = s[0] * kr0.x;
        float a1 = s[1] * kr0.y;
        a0 = fmaf(s[2], kr0.z, a0);
        a1 = fmaf(s[3], kr0.w, a1);
        a0 = fmaf(s[4], kr1.x, a0);
        a1 = fmaf(s[5], kr1.y, a1);
        a0 = fmaf(s[6], kr1.z, a0);
        a1 = fmaf(s[7], kr1.w, a1);
        float kdot = a0 + a1;
        kdot += __shfl_xor_sync(0xffffffffu, kdot, 1);
        kdot += __shfl_xor_sync(0xffffffffu, kdot, 2);
        kdot += __shfl_xor_sync(0xffffffffu, kdot, 4);
        kdot += __shfl_xor_sync(0xffffffffu, kdot, 8);

        float be = bt * (vv - kdot);

        s[0] = fmaf(be, kr0.x, s[0]);
        s[1] = fmaf(be, kr0.y, s[1]);
        s[2] = fmaf(be, kr0.z, s[2]);
        s[3] = fmaf(be, kr0.w, s[3]);
        s[4] = fmaf(be, kr1.x, s[4]);
        s[5] = fmaf(be, kr1.y, s[5]);
        s[6] = fmaf(be, kr1.z, s[6]);
        s[7] = fmaf(be, kr1.w, s[7]);

        float o0 = s[0] * qq0.x;
        float o1 = s[1] * qq0.y;
        o0 = fmaf(s[2], qq0.z, o0);
        o1 = fmaf(s[3], qq0.w, o1);
        o0 = fmaf(s[4], qq1.x, o0);
        o1 = fmaf(s[5], qq1.y, o1);
        o0 = fmaf(s[6], qq1.z, o0);
        o1 = fmaf(s[7], qq1.w, o1);
        float od = o0 + o1;
        od += __shfl_xor_sync(0xffffffffu, od, 1);
        od += __shfl_xor_sync(0xffffffffu, od, 2);
        od += __shfl_xor_sync(0xffffffffu, od, 4);
        od += __shfl_xor_sync(0xffffffffu, od, 8);

        if (ks == 0) ob[(size_t)t * 2048] = od * scale;
    }
}

// ---------------- per-head LayerNorm + sigmoid gate + split to bf16 hi/lo ----------------
__global__ void ln_gate(const float* __restrict__ ln_w, const float* __restrict__ ln_b) {
    int gwarp = (int)(((size_t)blockIdx.x * blockDim.x + threadIdx.x) >> 5);
    int lane = threadIdx.x & 31;
    if (gwarp >= M_ * H_) return;
    int h = gwarp & 15;
    size_t r = (size_t)(gwarp >> 4);

    const float* obp = g_oscan + r * 2048 + h * 128;
    float4 o4 = *(const float4*)(obp + lane * 4);
    float sum = o4.x + o4.y + o4.z + o4.w;
#pragma unroll
    for (int off = 16; off; off >>= 1) sum += __shfl_xor_sync(0xffffffffu, sum, off);
    float mu = sum * (1.f / 128.f);
    float dx = o4.x - mu, dy = o4.y - mu, dz = o4.z - mu, dw = o4.w - mu;
    float sq = dx * dx + dy * dy + dz * dz + dw * dw;
#pragma unroll
    for (int off = 16; off; off >>= 1) sq += __shfl_xor_sync(0xffffffffu, sq, off);
    float rs = rsqrtf(sq * (1.f / 128.f) + 1e-5f);

    float vals[4] = {dx, dy, dz, dw};
#pragma unroll
    for (int e = 0; e < 4; e++) {
        int jj = lane * 4 + e;
        float y = vals[e] * rs * ln_w[jj] + ln_b[jj];
        float gate = sigf(g_P[r * (size_t)NP + CG + h * 128 + jj]);
        y *= gate;
        size_t idx = r * 2048 + h * 128 + jj;
        __nv_bfloat16 hh = __float2bfloat16(y);
        g_yh[idx] = hh;
        g_yl[idx] = __float2bfloat16(y - __bfloat162float(hh));
    }
}

// ---------------- launch ----------------
extern "C" void kernel_launch(void* const* d_in, const int* in_sizes, int n_in,
                              void* d_out, int out_size) {
    const float* x    = (const float*)d_in[0];
    const float* Wq   = (const float*)d_in[1];
    const float* Wk   = (const float*)d_in[2];
    const float* Wv   = (const float*)d_in[3];
    const float* Wa   = (const float*)d_in[4];
    const float* ba   = (const float*)d_in[5];
    const float* Wb   = (const float*)d_in[6];
    const float* bb   = (const float*)d_in[7];
    const float* Wg   = (const float*)d_in[8];
    const float* Wo   = (const float*)d_in[9];
    const float* cqw  = (const float*)d_in[10];
    const float* cqb  = (const float*)d_in[11];
    const float* ckw  = (const float*)d_in[12];
    const float* ckb  = (const float*)d_in[13];
    const float* cvw  = (const float*)d_in[14];
    const float* cvb  = (const float*)d_in[15];
    const float* ln_w = (const float*)d_in[16];
    const float* ln_b = (const float*)d_in[17];
    float* out = (float*)d_out;

    static __nv_bfloat16 *pxh = nullptr, *pxl, *pWh, *pWl, *pyh, *pyl, *pW2h, *pW2l;
    static float *pP;
    if (!pxh) {
        cudaGetSymbolAddress((void**)&pxh, g_xh);
        cudaGetSymbolAddress((void**)&pxl, g_xl);
        cudaGetSymbolAddress((void**)&pWh, g_Wh);
        cudaGetSymbolAddress((void**)&pWl, g_Wl);
        cudaGetSymbolAddress((void**)&pP,  g_P);
        cudaGetSymbolAddress((void**)&pyh, g_yh);
        cudaGetSymbolAddress((void**)&pyl, g_yl);
        cudaGetSymbolAddress((void**)&pW2h, g_W2h);
        cudaGetSymbolAddress((void**)&pW2l, g_W2l);
        cudaFuncSetAttribute(gemm_split, cudaFuncAttributeMaxDynamicSharedMemorySize, 65536);
    }

    const int TPB = 256;

    // 1) split inputs to bf16 hi/lo (vectorized)
    split_f32_v4<<<(int)(((size_t)M_ * D_ / 4 + TPB - 1) / TPB), TPB>>>(x, pxh, pxl, (size_t)M_ * D_ / 4);
    build_wcat<<<(int)(((size_t)NP * D_ / 4 + TPB - 1) / TPB), TPB>>>(Wq, Wk, Wv, Wa, Wg, Wb);
    split_f32_v4<<<(int)(((size_t)D_ * 2048 / 4 + TPB - 1) / TPB), TPB>>>(Wo, pW2h, pW2l, (size_t)D_ * 2048 / 4);

    // 2) fused projection GEMM: P = x @ Wcat^T   (8192 x 10368 x 2048)
    gemm_split<<<dim3(NP / 128, M_ / 128), 256, 65536>>>(pxh, pxl, pWh, pWl, pP, M_, NP, D_);

    // 3) depthwise causal conv + SiLU on q,k,v
    conv_silu<<<(int)(((size_t)M_ * 6144 + TPB - 1) / TPB), TPB>>>(cqw, cqb, ckw, ckb, cvw, cvb);

    // 4) decay / beta
    decay_kernel<<<(int)(((size_t)M_ * 2048 + TPB - 1) / TPB), TPB>>>(ba);
    beta_kernel<<<(int)(((size_t)M_ * H_ + TPB - 1) / TPB), TPB>>>(bb);

    // 5) gated delta-rule scan (4096 warps: 64 per (b,h))
    kda_scan<<<dim3(B_ * H_, 16), 128>>>();

    // 6) LayerNorm + gate + bf16 split
    ln_gate<<<M_ * H_ / 8, 256>>>(ln_w, ln_b);

    // 7) output projection: out = y @ Wo^T   (8192 x 2048 x 2048)
    gemm_split<<<dim3(2048 / 128, M_ / 128), 256, 65536>>>(pyh, pyl, pW2h, pW2l, out, M_, 2048, D_);
}